// round 1
// baseline (speedup 1.0000x reference)
#include <cuda_runtime.h>
#include <cuda_bf16.h>
#include <cstddef>

// Problem constants
#define BATCH   4
#define SEQ     4096
#define DMODEL  1024
#define DSTATE  16
#define DINNER  2048
#define BL      (BATCH*SEQ)          // 16384 rows

// ---------------------------------------------------------------------------
// Scratch (device globals; allocation APIs are forbidden)
// ---------------------------------------------------------------------------
__device__ float g_xr[(size_t)BL * (2*DINNER)];   // 256 MB : x @ W_in  (main | res)
__device__ float g_xc[(size_t)BL * DINNER];       // 128 MB : conv+silu output
__device__ float g_bc[(size_t)BL * 32];           //   2 MB : [Bt | Ct] per row
__device__ float g_ys[(size_t)BL];                //  64 KB : scan scalar output
__device__ float g_y [(size_t)BL * DINNER];       // 128 MB : gated activation

// ---------------------------------------------------------------------------
// Generic fp32 SGEMM: C[M,N] = A[M,K] * B[K,N], row-major, exact-fit tiles.
// 128x128 block tile, K-tile 8, 256 threads, 8x8 per-thread microtile.
// ---------------------------------------------------------------------------
__global__ __launch_bounds__(256, 2)
void sgemm128(const float* __restrict__ A, const float* __restrict__ B,
              float* __restrict__ C, int M, int N, int K)
{
    __shared__ float As[8][128];
    __shared__ float Bs[8][128];

    const int bx  = blockIdx.x;           // N tile
    const int by  = blockIdx.y;           // M tile
    const int tid = threadIdx.x;

    // A tile loader: 128 rows x 8 k; each thread one float4 (row-major A)
    const int arow  = tid >> 1;
    const int acol4 = (tid & 1) * 4;
    // B tile loader: 8 rows x 128 cols; each thread one float4
    const int brow  = tid >> 5;
    const int bcol4 = (tid & 31) * 4;

    const int ty = tid >> 4;   // 0..15
    const int tx = tid & 15;   // 0..15

    float acc[8][8];
#pragma unroll
    for (int i = 0; i < 8; i++)
#pragma unroll
        for (int j = 0; j < 8; j++) acc[i][j] = 0.f;

    const float* Ab = A + (size_t)(by * 128) * K;
    const float* Bb = B + (size_t)(bx * 128);

    for (int k0 = 0; k0 < K; k0 += 8) {
        float4 av = *(const float4*)(Ab + (size_t)arow * K + k0 + acol4);
        float4 bv = *(const float4*)(Bb + (size_t)(k0 + brow) * N + bcol4);
        __syncthreads();   // previous tile's reads complete before overwrite
        As[acol4 + 0][arow] = av.x;
        As[acol4 + 1][arow] = av.y;
        As[acol4 + 2][arow] = av.z;
        As[acol4 + 3][arow] = av.w;
        *(float4*)&Bs[brow][bcol4] = bv;
        __syncthreads();

#pragma unroll
        for (int kk = 0; kk < 8; kk++) {
            float4 a0 = *(const float4*)&As[kk][ty * 8];
            float4 a1 = *(const float4*)&As[kk][ty * 8 + 4];
            float4 b0 = *(const float4*)&Bs[kk][tx * 8];
            float4 b1 = *(const float4*)&Bs[kk][tx * 8 + 4];
            float a[8] = {a0.x,a0.y,a0.z,a0.w,a1.x,a1.y,a1.z,a1.w};
            float b[8] = {b0.x,b0.y,b0.z,b0.w,b1.x,b1.y,b1.z,b1.w};
#pragma unroll
            for (int i = 0; i < 8; i++)
#pragma unroll
                for (int j = 0; j < 8; j++)
                    acc[i][j] += a[i] * b[j];
        }
    }

    float* Cb = C + (size_t)(by * 128 + ty * 8) * N + bx * 128 + tx * 8;
#pragma unroll
    for (int i = 0; i < 8; i++) {
        *(float4*)(Cb + (size_t)i * N)     = make_float4(acc[i][0], acc[i][1], acc[i][2], acc[i][3]);
        *(float4*)(Cb + (size_t)i * N + 4) = make_float4(acc[i][4], acc[i][5], acc[i][6], acc[i][7]);
    }
}

// ---------------------------------------------------------------------------
// Depthwise conv (k=3, pad 1, along seq) + bias + SiLU on the main half of xr.
// One thread per (row, channel).
// ---------------------------------------------------------------------------
__global__ void conv_silu(const float* __restrict__ conv_w, const float* __restrict__ conv_b)
{
    size_t idx = (size_t)blockIdx.x * 256 + threadIdx.x;   // over BL*DINNER
    int c   = (int)(idx & (DINNER - 1));
    size_t row = idx >> 11;                                // /DINNER
    int l = (int)(row & (SEQ - 1));

    float w0 = conv_w[c * 3 + 0];
    float w1 = conv_w[c * 3 + 1];
    float w2 = conv_w[c * 3 + 2];

    float acc = conv_b[c];
    if (l > 0)       acc += w0 * g_xr[(row - 1) * (size_t)(2*DINNER) + c];
    acc                  += w1 * g_xr[ row      * (size_t)(2*DINNER) + c];
    if (l < SEQ - 1) acc += w2 * g_xr[(row + 1) * (size_t)(2*DINNER) + c];

    float s = acc / (1.f + expf(-acc));
    g_xc[idx] = s;
}

// ---------------------------------------------------------------------------
// Skinny GEMM: [Bt|Ct] (BL x 32) = xc (BL x 2048) * [W_B | W_C] (2048 x 16 each)
// Block: 128 rows x 32 cols; 256 threads, each 16 rows of one column.
// ---------------------------------------------------------------------------
__global__ __launch_bounds__(256, 4)
void bc_gemm(const float* __restrict__ Wb, const float* __restrict__ Wc)
{
    __shared__ float xs[128][32];
    __shared__ float ws[32][32];

    const int row0 = blockIdx.x * 128;
    const int tid  = threadIdx.x;
    const int tx = tid & 31;   // output column (0..15 B, 16..31 C)
    const int ty = tid >> 5;   // row group (16 rows each)

    float acc[16];
#pragma unroll
    for (int r = 0; r < 16; r++) acc[r] = 0.f;

    for (int k0 = 0; k0 < DINNER; k0 += 32) {
        __syncthreads();
#pragma unroll
        for (int i = 0; i < 4; i++) {
            int lin = (tid + i * 256) * 4;
            int r = lin >> 5, c = lin & 31;
            float4 v = *(const float4*)&g_xc[(size_t)(row0 + r) * DINNER + k0 + c];
            *(float4*)&xs[r][c] = v;
        }
        {
            int lin = tid * 4;
            int kk = lin >> 5, c = lin & 31;
            float4 v;
            if (c < 16) v = *(const float4*)&Wb[(size_t)(k0 + kk) * 16 + c];
            else        v = *(const float4*)&Wc[(size_t)(k0 + kk) * 16 + (c - 16)];
            *(float4*)&ws[kk][c] = v;
        }
        __syncthreads();

#pragma unroll
        for (int kk = 0; kk < 32; kk++) {
            float w = ws[kk][tx];
#pragma unroll
            for (int r = 0; r < 16; r++)
                acc[r] += xs[ty * 16 + r][kk] * w;
        }
    }

#pragma unroll
    for (int r = 0; r < 16; r++)
        g_bc[(size_t)(row0 + ty * 16 + r) * 32 + tx] = acc[r];
}

// ---------------------------------------------------------------------------
// Sequential selective-state scan. One block per batch; smem-tiled Bt/Ct.
// state_s[l] = decay_s * state_s[l-1] + Bt[l,s];  ys[l] = sum_s state*Ct[l,s]
// decay_s = exp(-softplus(A_s)) = 1/(1+exp(A_s))
// ---------------------------------------------------------------------------
#define SCAN_TILE 256
__global__ void scan_kernel(const float* __restrict__ A)
{
    __shared__ float bcs[SCAN_TILE][32];
    const int b   = blockIdx.x;
    const int tid = threadIdx.x;   // 256 threads

    float dec = 0.f, st = 0.f;
    if (tid < DSTATE) dec = 1.f / (1.f + expf(A[tid]));

    const size_t base = (size_t)b * SEQ;

    for (int t0 = 0; t0 < SEQ; t0 += SCAN_TILE) {
        // cooperative load of [Bt|Ct] tile: thread t loads its own row
        const size_t grow = (base + t0 + tid) * 32;
#pragma unroll
        for (int i = 0; i < 8; i++)
            *(float4*)&bcs[tid][i * 4] = *(const float4*)&g_bc[grow + i * 4];
        __syncthreads();

        if (tid < DSTATE) {
            for (int l = 0; l < SCAN_TILE; l++) {
                st = fmaf(st, dec, bcs[l][tid]);
                float v = st * bcs[l][16 + tid];
#pragma unroll
                for (int m = 8; m >= 1; m >>= 1)
                    v += __shfl_xor_sync(0x0000ffffu, v, m, 16);
                if (tid == 0) g_ys[base + t0 + l] = v;
            }
        }
        __syncthreads();
    }
}

// ---------------------------------------------------------------------------
// Gating elementwise: y = (ys + xc*D) * silu(res)
// ---------------------------------------------------------------------------
__global__ void gate_y(const float* __restrict__ Dv)
{
    size_t idx = (size_t)blockIdx.x * 256 + threadIdx.x;   // over BL*DINNER
    int c = (int)(idx & (DINNER - 1));
    size_t row = idx >> 11;

    float xc  = g_xc[idx];
    float ysv = g_ys[row];
    float res = g_xr[row * (size_t)(2*DINNER) + DINNER + c];
    float sr  = res / (1.f + expf(-res));
    g_y[idx] = (ysv + xc * Dv[c]) * sr;
}

// ---------------------------------------------------------------------------
// Launch
// ---------------------------------------------------------------------------
extern "C" void kernel_launch(void* const* d_in, const int* in_sizes, int n_in,
                              void* d_out, int out_size)
{
    const float* x      = (const float*)d_in[0];
    const float* W_in   = (const float*)d_in[1];
    const float* conv_w = (const float*)d_in[2];
    const float* conv_b = (const float*)d_in[3];
    const float* W_B    = (const float*)d_in[4];
    const float* W_C    = (const float*)d_in[5];
    const float* A      = (const float*)d_in[6];
    const float* Dv     = (const float*)d_in[7];
    const float* W_out  = (const float*)d_in[8];
    float* out = (float*)d_out;

    float *xr_p, *y_p;
    cudaGetSymbolAddress((void**)&xr_p, g_xr);
    cudaGetSymbolAddress((void**)&y_p,  g_y);

    // 1) xr = x @ W_in   (16384 x 4096, K=1024)
    {
        dim3 grid((2*DINNER) / 128, BL / 128);
        sgemm128<<<grid, 256>>>(x, W_in, xr_p, BL, 2*DINNER, DMODEL);
    }
    // 2) depthwise conv + bias + silu -> xc
    conv_silu<<<(BL * (size_t)DINNER) / 256, 256>>>(conv_w, conv_b);
    // 3) [Bt|Ct] = xc @ [W_B|W_C]
    bc_gemm<<<BL / 128, 256>>>(W_B, W_C);
    // 4) sequential scan -> ys
    scan_kernel<<<BATCH, 256>>>(A);
    // 5) gating elementwise -> y
    gate_y<<<(BL * (size_t)DINNER) / 256, 256>>>(Dv);
    // 6) out = y @ W_out  (16384 x 1024, K=2048)
    {
        dim3 grid(DMODEL / 128, BL / 128);
        sgemm128<<<grid, 256>>>(y_p, W_out, out, BL, DMODEL, DINNER);
    }
}

// round 2
// speedup vs baseline: 2.7491x; 2.7491x over previous
#include <cuda_runtime.h>
#include <cuda_bf16.h>
#include <cstddef>
#include <cstdint>

// Problem constants
#define BATCH   4
#define SEQ     4096
#define DMODEL  1024
#define DSTATE  16
#define DINNER  2048
#define BL      (BATCH*SEQ)          // 16384 rows
#define NCHUNK  32                   // SEQ/128 scan chunks
#define CHUNK   128

// ---------------------------------------------------------------------------
// Scratch (device globals; allocation APIs are forbidden)
// ---------------------------------------------------------------------------
__device__ float g_xr[(size_t)BL * (2*DINNER)];   // x @ W_in (main | res)
__device__ float g_xc[(size_t)BL * DINNER];       // conv+silu output
__device__ float g_bc[(size_t)BL * 32];           // [Bt | Ct] per row
__device__ float g_ys[(size_t)BL];                // scan scalar output
__device__ float g_y [(size_t)BL * DINNER];       // gated activation
__device__ float g_E   [BATCH * NCHUNK * DSTATE]; // per-chunk end states
__device__ float g_init[BATCH * NCHUNK * DSTATE]; // per-chunk initial states

// ---------------------------------------------------------------------------
// TF32 tensor-core GEMM: C[M,N] = A[M,K] * B[K,N], row-major.
// 128x128 block tile, BK=16, 256 threads (8 warps as 2x4),
// warp tile 64x32, mma.m16n8k8.tf32, cp.async double buffering.
// ---------------------------------------------------------------------------
#define BM 128
#define BN 128
#define BKT 16
#define ASTR 20    // A smem row stride in floats (16 + 4 pad -> conflict-free frag loads)
#define BSTR 136   // B smem row stride in floats (128 + 8 pad -> conflict-free frag loads)

__device__ __forceinline__ uint32_t f2tf(float f) {
    uint32_t r;
    asm("cvt.rna.tf32.f32 %0, %1;" : "=r"(r) : "f"(f));
    return r;
}

__device__ __forceinline__ void cpa16(float* dst_smem, const float* src_gmem) {
    uint32_t d = (uint32_t)__cvta_generic_to_shared(dst_smem);
    asm volatile("cp.async.ca.shared.global [%0], [%1], 16;" :: "r"(d), "l"(src_gmem));
}

__device__ __forceinline__ void mma_tf32(float d[4], const uint32_t a[4], const uint32_t b[2]) {
    asm volatile(
        "mma.sync.aligned.m16n8k8.row.col.f32.tf32.tf32.f32 "
        "{%0,%1,%2,%3}, {%4,%5,%6,%7}, {%8,%9}, {%0,%1,%2,%3};\n"
        : "+f"(d[0]), "+f"(d[1]), "+f"(d[2]), "+f"(d[3])
        : "r"(a[0]), "r"(a[1]), "r"(a[2]), "r"(a[3]), "r"(b[0]), "r"(b[1]));
}

__global__ __launch_bounds__(256)
void tf32gemm(const float* __restrict__ A, const float* __restrict__ B,
              float* __restrict__ C, int M, int N, int K)
{
    __shared__ float As[2][BM * ASTR];
    __shared__ float Bs[2][BKT * BSTR];

    const int tid  = threadIdx.x;
    const int lane = tid & 31;
    const int wid  = tid >> 5;
    const int wm   = wid >> 2;   // 0..1 (64 rows each)
    const int wn   = wid & 3;    // 0..3 (32 cols each)
    const int m0   = blockIdx.y * BM;
    const int n0   = blockIdx.x * BN;

    float acc[4][4][4];
#pragma unroll
    for (int mi = 0; mi < 4; mi++)
#pragma unroll
        for (int ni = 0; ni < 4; ni++)
#pragma unroll
            for (int r = 0; r < 4; r++) acc[mi][ni][r] = 0.f;

    const int NT = K / BKT;

    auto issue = [&](int kt, int buf) {
        const float* Ag = A + (size_t)m0 * K + kt * BKT;
#pragma unroll
        for (int i = 0; i < 2; i++) {
            int idx = tid + i * 256;           // 512 float4s over 128x16
            int r = idx >> 2, kq = (idx & 3) * 4;
            cpa16(&As[buf][r * ASTR + kq], Ag + (size_t)r * K + kq);
        }
        const float* Bg = B + (size_t)(kt * BKT) * N + n0;
#pragma unroll
        for (int i = 0; i < 2; i++) {
            int idx = tid + i * 256;           // 512 float4s over 16x128
            int kr = idx >> 5, nq = (idx & 31) * 4;
            cpa16(&Bs[buf][kr * BSTR + nq], Bg + (size_t)kr * N + nq);
        }
        asm volatile("cp.async.commit_group;");
    };

    issue(0, 0);

    for (int kt = 0; kt < NT; kt++) {
        if (kt + 1 < NT) {
            issue(kt + 1, (kt + 1) & 1);
            asm volatile("cp.async.wait_group 1;");
        } else {
            asm volatile("cp.async.wait_group 0;");
        }
        __syncthreads();

        const float* as = As[kt & 1];
        const float* bs = Bs[kt & 1];

#pragma unroll
        for (int ks = 0; ks < BKT; ks += 8) {
            uint32_t af[4][4], bf[4][2];
            const int g = lane >> 2;     // group id
            const int t = lane & 3;      // thread-in-group
            const int ak = ks + t;
#pragma unroll
            for (int mi = 0; mi < 4; mi++) {
                int r = wm * 64 + mi * 16 + g;
                af[mi][0] = f2tf(as[r * ASTR + ak]);
                af[mi][1] = f2tf(as[(r + 8) * ASTR + ak]);
                af[mi][2] = f2tf(as[r * ASTR + ak + 4]);
                af[mi][3] = f2tf(as[(r + 8) * ASTR + ak + 4]);
            }
#pragma unroll
            for (int ni = 0; ni < 4; ni++) {
                int n = wn * 32 + ni * 8 + g;
                bf[ni][0] = f2tf(bs[ak * BSTR + n]);
                bf[ni][1] = f2tf(bs[(ak + 4) * BSTR + n]);
            }
#pragma unroll
            for (int mi = 0; mi < 4; mi++)
#pragma unroll
                for (int ni = 0; ni < 4; ni++)
                    mma_tf32(acc[mi][ni], af[mi], bf[ni]);
        }
        __syncthreads();
    }

    // Epilogue: c0 at (g, 2t), c1 (g, 2t+1), c2 (g+8, 2t), c3 (g+8, 2t+1)
    const int g = lane >> 2, t = lane & 3;
#pragma unroll
    for (int mi = 0; mi < 4; mi++) {
#pragma unroll
        for (int ni = 0; ni < 4; ni++) {
            int r = m0 + wm * 64 + mi * 16 + g;
            int c = n0 + wn * 32 + ni * 8 + t * 2;
            *(float2*)&C[(size_t)r * N + c]       = make_float2(acc[mi][ni][0], acc[mi][ni][1]);
            *(float2*)&C[(size_t)(r + 8) * N + c] = make_float2(acc[mi][ni][2], acc[mi][ni][3]);
        }
    }
}

// ---------------------------------------------------------------------------
// Depthwise conv (k=3, pad 1, along seq) + bias + SiLU on the main half of xr.
// ---------------------------------------------------------------------------
__global__ void conv_silu(const float* __restrict__ conv_w, const float* __restrict__ conv_b)
{
    size_t idx = (size_t)blockIdx.x * 256 + threadIdx.x;   // over BL*DINNER
    int c   = (int)(idx & (DINNER - 1));
    size_t row = idx >> 11;                                // /DINNER
    int l = (int)(row & (SEQ - 1));

    float w0 = conv_w[c * 3 + 0];
    float w1 = conv_w[c * 3 + 1];
    float w2 = conv_w[c * 3 + 2];

    float acc = conv_b[c];
    if (l > 0)       acc += w0 * g_xr[(row - 1) * (size_t)(2*DINNER) + c];
    acc                  += w1 * g_xr[ row      * (size_t)(2*DINNER) + c];
    if (l < SEQ - 1) acc += w2 * g_xr[(row + 1) * (size_t)(2*DINNER) + c];

    float s = acc / (1.f + expf(-acc));
    g_xc[idx] = s;
}

// ---------------------------------------------------------------------------
// Skinny GEMM: [Bt|Ct] (BL x 32) = xc (BL x 2048) * [W_B | W_C]
// ---------------------------------------------------------------------------
__global__ __launch_bounds__(256, 4)
void bc_gemm(const float* __restrict__ Wb, const float* __restrict__ Wc)
{
    __shared__ float xs[128][32];
    __shared__ float ws[32][32];

    const int row0 = blockIdx.x * 128;
    const int tid  = threadIdx.x;
    const int tx = tid & 31;   // output column (0..15 B, 16..31 C)
    const int ty = tid >> 5;   // row group (16 rows each)

    float acc[16];
#pragma unroll
    for (int r = 0; r < 16; r++) acc[r] = 0.f;

    for (int k0 = 0; k0 < DINNER; k0 += 32) {
        __syncthreads();
#pragma unroll
        for (int i = 0; i < 4; i++) {
            int lin = (tid + i * 256) * 4;
            int r = lin >> 5, c = lin & 31;
            float4 v = *(const float4*)&g_xc[(size_t)(row0 + r) * DINNER + k0 + c];
            *(float4*)&xs[r][c] = v;
        }
        {
            int lin = tid * 4;
            int kk = lin >> 5, c = lin & 31;
            float4 v;
            if (c < 16) v = *(const float4*)&Wb[(size_t)(k0 + kk) * 16 + c];
            else        v = *(const float4*)&Wc[(size_t)(k0 + kk) * 16 + (c - 16)];
            *(float4*)&ws[kk][c] = v;
        }
        __syncthreads();

#pragma unroll
        for (int kk = 0; kk < 32; kk++) {
            float w = ws[kk][tx];
#pragma unroll
            for (int r = 0; r < 16; r++)
                acc[r] += xs[ty * 16 + r][kk] * w;
        }
    }

#pragma unroll
    for (int r = 0; r < 16; r++)
        g_bc[(size_t)(row0 + ty * 16 + r) * 32 + tx] = acc[r];
}

// ---------------------------------------------------------------------------
// Chunked scan.
// Phase A: per-chunk end state starting from 0.
// Combine: sequential over chunks (tiny) -> per-chunk initial states.
// Phase C: replay each chunk from its true initial state, emit outputs.
// ---------------------------------------------------------------------------
__global__ void scan_phaseA(const float* __restrict__ A)
{
    __shared__ float bcs[CHUNK][32];
    const int b = blockIdx.x >> 5;       // batch
    const int c = blockIdx.x & 31;       // chunk
    const int tid = threadIdx.x;         // 128

    const size_t base = (size_t)b * SEQ + (size_t)c * CHUNK;
    const size_t grow = (base + tid) * 32;
#pragma unroll
    for (int i = 0; i < 8; i++)
        *(float4*)&bcs[tid][i * 4] = *(const float4*)&g_bc[grow + i * 4];
    __syncthreads();

    if (tid < DSTATE) {
        float dec = 1.f / (1.f + expf(A[tid]));
        float st = 0.f;
        for (int l = 0; l < CHUNK; l++)
            st = fmaf(st, dec, bcs[l][tid]);
        g_E[(b * NCHUNK + c) * DSTATE + tid] = st;
    }
}

__global__ void scan_combine(const float* __restrict__ A)
{
    const int b = blockIdx.x;            // BATCH blocks, 16 threads
    const int s = threadIdx.x;
    float dec  = 1.f / (1.f + expf(A[s]));
    float d128 = powf(dec, (float)CHUNK);
    float S = 0.f;
    for (int c = 0; c < NCHUNK; c++) {
        g_init[(b * NCHUNK + c) * DSTATE + s] = S;
        S = S * d128 + g_E[(b * NCHUNK + c) * DSTATE + s];
    }
}

__global__ void scan_phaseC(const float* __restrict__ A)
{
    __shared__ float bcs[CHUNK][32];
    const int b = blockIdx.x >> 5;
    const int c = blockIdx.x & 31;
    const int tid = threadIdx.x;

    const size_t base = (size_t)b * SEQ + (size_t)c * CHUNK;
    const size_t grow = (base + tid) * 32;
#pragma unroll
    for (int i = 0; i < 8; i++)
        *(float4*)&bcs[tid][i * 4] = *(const float4*)&g_bc[grow + i * 4];
    __syncthreads();

    if (tid < DSTATE) {
        float dec = 1.f / (1.f + expf(A[tid]));
        float st = g_init[(b * NCHUNK + c) * DSTATE + tid];
        for (int l = 0; l < CHUNK; l++) {
            st = fmaf(st, dec, bcs[l][tid]);
            float v = st * bcs[l][16 + tid];
#pragma unroll
            for (int m = 8; m >= 1; m >>= 1)
                v += __shfl_xor_sync(0x0000ffffu, v, m, 16);
            if (tid == 0) g_ys[base + l] = v;
        }
    }
}

// ---------------------------------------------------------------------------
// Gating elementwise: y = (ys + xc*D) * silu(res)
// ---------------------------------------------------------------------------
__global__ void gate_y(const float* __restrict__ Dv)
{
    size_t idx = (size_t)blockIdx.x * 256 + threadIdx.x;   // over BL*DINNER
    int c = (int)(idx & (DINNER - 1));
    size_t row = idx >> 11;

    float xc  = g_xc[idx];
    float ysv = g_ys[row];
    float res = g_xr[row * (size_t)(2*DINNER) + DINNER + c];
    float sr  = res / (1.f + expf(-res));
    g_y[idx] = (ysv + xc * Dv[c]) * sr;
}

// ---------------------------------------------------------------------------
// Launch
// ---------------------------------------------------------------------------
extern "C" void kernel_launch(void* const* d_in, const int* in_sizes, int n_in,
                              void* d_out, int out_size)
{
    const float* x      = (const float*)d_in[0];
    const float* W_in   = (const float*)d_in[1];
    const float* conv_w = (const float*)d_in[2];
    const float* conv_b = (const float*)d_in[3];
    const float* W_B    = (const float*)d_in[4];
    const float* W_C    = (const float*)d_in[5];
    const float* A      = (const float*)d_in[6];
    const float* Dv     = (const float*)d_in[7];
    const float* W_out  = (const float*)d_in[8];
    float* out = (float*)d_out;

    float *xr_p, *y_p;
    cudaGetSymbolAddress((void**)&xr_p, g_xr);
    cudaGetSymbolAddress((void**)&y_p,  g_y);

    // 1) xr = x @ W_in   (16384 x 4096, K=1024)  [TF32 tensor cores]
    {
        dim3 grid((2*DINNER) / BN, BL / BM);
        tf32gemm<<<grid, 256>>>(x, W_in, xr_p, BL, 2*DINNER, DMODEL);
    }
    // 2) depthwise conv + bias + silu -> xc
    conv_silu<<<(BL * (size_t)DINNER) / 256, 256>>>(conv_w, conv_b);
    // 3) [Bt|Ct] = xc @ [W_B|W_C]
    bc_gemm<<<BL / 128, 256>>>(W_B, W_C);
    // 4) chunked scan -> ys
    scan_phaseA<<<BATCH * NCHUNK, CHUNK>>>(A);
    scan_combine<<<BATCH, DSTATE>>>(A);
    scan_phaseC<<<BATCH * NCHUNK, CHUNK>>>(A);
    // 5) gating elementwise -> y
    gate_y<<<(BL * (size_t)DINNER) / 256, 256>>>(Dv);
    // 6) out = y @ W_out  (16384 x 1024, K=2048)  [TF32 tensor cores]
    {
        dim3 grid(DMODEL / BN, BL / BM);
        tf32gemm<<<grid, 256>>>(y_p, W_out, out, BL, DMODEL, DINNER);
    }
}